// round 3
// baseline (speedup 1.0000x reference)
#include <cuda_runtime.h>
#include <math.h>

#define H_DIM 1024
#define FFN_DIM 4096
#define B_ROWS 4096
#define D_IN 784
#define D_OUT 1000
#define N_STEPS 30
#define GAMMA 0.5f
#define LN_EPS 1e-5f

// Scratch (device globals; no allocation allowed)
__device__ float g_h[(size_t)B_ROWS * H_DIM];      // 16 MB
__device__ float g_xemb[(size_t)B_ROWS * H_DIM];   // 16 MB
__device__ float g_hn[(size_t)B_ROWS * H_DIM];     // 16 MB
__device__ float g_ffn[(size_t)B_ROWS * FFN_DIM];  // 64 MB

// ---------------------------------------------------------------------------
// SGEMM: C[M,N] = epilogue( A[M,K] @ W[N,K]^T + bias[N] )
// 128x128 block tile, BK=8, 256 threads, 8x8 per-thread microkernel.
// MODE 0: C = v; optionally C2 = v (dual write for embed)
// MODE 1: C = tanhf(v)
// MODE 2: C = (1-GAMMA)*Hold + GAMMA*(v + Xemb)
// M assumed multiple of 128, K multiple of 8. N arbitrary (guarded).
// ---------------------------------------------------------------------------
template <int MODE>
__global__ __launch_bounds__(256)
void sgemm_kernel(const float* __restrict__ A,
                  const float* __restrict__ W,
                  const float* __restrict__ bias,
                  float* __restrict__ C,
                  float* __restrict__ C2,
                  const float* __restrict__ Hold,
                  const float* __restrict__ Xemb,
                  int M, int N, int K)
{
    __shared__ float As[8][128];
    __shared__ float Bs[8][128];

    const int tid = threadIdx.x;
    const int bm = blockIdx.y * 128;
    const int bn = blockIdx.x * 128;

    // global->shared load mapping: 256 threads, each one float4 per tile
    const int lrow = tid >> 1;          // 0..127
    const int lk   = (tid & 1) * 4;     // 0 or 4

    const float* Aptr = A + (size_t)(bm + lrow) * K + lk;
    const float* Wptr = W + (size_t)(bn + lrow) * K + lk;
    const bool wvalid = (bn + lrow) < N;

    const int tx = tid & 15;   // 0..15 -> columns
    const int ty = tid >> 4;   // 0..15 -> rows

    float acc[8][8];
    #pragma unroll
    for (int i = 0; i < 8; i++)
        #pragma unroll
        for (int j = 0; j < 8; j++)
            acc[i][j] = 0.0f;

    for (int k0 = 0; k0 < K; k0 += 8) {
        float4 av = *(const float4*)(Aptr + k0);
        float4 wv = wvalid ? *(const float4*)(Wptr + k0)
                           : make_float4(0.f, 0.f, 0.f, 0.f);
        __syncthreads();
        As[lk + 0][lrow] = av.x; As[lk + 1][lrow] = av.y;
        As[lk + 2][lrow] = av.z; As[lk + 3][lrow] = av.w;
        Bs[lk + 0][lrow] = wv.x; Bs[lk + 1][lrow] = wv.y;
        Bs[lk + 2][lrow] = wv.z; Bs[lk + 3][lrow] = wv.w;
        __syncthreads();

        #pragma unroll
        for (int kk = 0; kk < 8; kk++) {
            float af[8], bf[8];
            *(float4*)&af[0] = *(const float4*)&As[kk][ty * 4];
            *(float4*)&af[4] = *(const float4*)&As[kk][ty * 4 + 64];
            *(float4*)&bf[0] = *(const float4*)&Bs[kk][tx * 4];
            *(float4*)&bf[4] = *(const float4*)&Bs[kk][tx * 4 + 64];
            #pragma unroll
            for (int i = 0; i < 8; i++)
                #pragma unroll
                for (int j = 0; j < 8; j++)
                    acc[i][j] = fmaf(af[i], bf[j], acc[i][j]);
        }
    }

    // epilogue
    int rows[8], cols[8];
    #pragma unroll
    for (int i = 0; i < 4; i++) {
        rows[i]     = bm + ty * 4 + i;
        rows[i + 4] = bm + 64 + ty * 4 + i;
        cols[i]     = bn + tx * 4 + i;
        cols[i + 4] = bn + 64 + tx * 4 + i;
    }
    float bj[8];
    #pragma unroll
    for (int j = 0; j < 8; j++)
        bj[j] = (cols[j] < N) ? bias[cols[j]] : 0.0f;

    #pragma unroll
    for (int i = 0; i < 8; i++) {
        const size_t rbase = (size_t)rows[i] * N;
        #pragma unroll
        for (int j = 0; j < 8; j++) {
            if (cols[j] < N) {
                const size_t idx = rbase + cols[j];
                float v = acc[i][j] + bj[j];
                if (MODE == 0) {
                    C[idx] = v;
                    if (C2) C2[idx] = v;
                } else if (MODE == 1) {
                    C[idx] = tanhf(v);
                } else {  // MODE 2
                    C[idx] = (1.0f - GAMMA) * Hold[idx] + GAMMA * (v + Xemb[idx]);
                }
            }
        }
    }
}

// ---------------------------------------------------------------------------
// LayerNorm over rows of [B_ROWS, 1024]; one block (256 threads) per row.
// ---------------------------------------------------------------------------
__global__ __launch_bounds__(256)
void layernorm_kernel(const float* __restrict__ Hin,
                      const float* __restrict__ w,
                      const float* __restrict__ b,
                      float* __restrict__ Out)
{
    __shared__ float ssum[8], ssq[8];
    const int row = blockIdx.x;
    const int tid = threadIdx.x;

    const float4* hp = (const float4*)(Hin + (size_t)row * H_DIM);
    float4 v = hp[tid];
    float s = v.x + v.y + v.z + v.w;
    float q = v.x * v.x + v.y * v.y + v.z * v.z + v.w * v.w;
    #pragma unroll
    for (int o = 16; o > 0; o >>= 1) {
        s += __shfl_xor_sync(0xFFFFFFFFu, s, o);
        q += __shfl_xor_sync(0xFFFFFFFFu, q, o);
    }
    const int warp = tid >> 5, lane = tid & 31;
    if (lane == 0) { ssum[warp] = s; ssq[warp] = q; }
    __syncthreads();
    float ts = 0.f, tq = 0.f;
    #pragma unroll
    for (int i = 0; i < 8; i++) { ts += ssum[i]; tq += ssq[i]; }

    const float mu  = ts * (1.0f / H_DIM);
    const float var = tq * (1.0f / H_DIM) - mu * mu;
    const float inv = rsqrtf(var + LN_EPS);

    float4 wv = ((const float4*)w)[tid];
    float4 bv = ((const float4*)b)[tid];
    float4 o;
    o.x = (v.x - mu) * inv * wv.x + bv.x;
    o.y = (v.y - mu) * inv * wv.y + bv.y;
    o.z = (v.z - mu) * inv * wv.z + bv.z;
    o.w = (v.w - mu) * inv * wv.w + bv.w;
    ((float4*)(Out + (size_t)row * H_DIM))[tid] = o;
}

// ---------------------------------------------------------------------------
extern "C" void kernel_launch(void* const* d_in, const int* in_sizes, int n_in,
                              void* d_out, int out_size)
{
    const float* x       = (const float*)d_in[0];   // [4096, 784]
    const float* embed_w = (const float*)d_in[1];   // [1024, 784]
    const float* embed_b = (const float*)d_in[2];   // [1024]
    const float* W1_w    = (const float*)d_in[3];   // [4096, 1024]
    const float* W1_b    = (const float*)d_in[4];   // [4096]
    const float* W2_w    = (const float*)d_in[5];   // [1024, 4096]
    const float* W2_b    = (const float*)d_in[6];   // [1024]
    const float* norm_w  = (const float*)d_in[7];   // [1024]
    const float* norm_b  = (const float*)d_in[8];   // [1024]
    const float* head_w  = (const float*)d_in[9];   // [1000, 1024]
    const float* head_b  = (const float*)d_in[10];  // [1000]
    // d_in[11] = steps (device scalar; fixed at 30 by the problem setup)

    float* out = (float*)d_out;                     // [4096, 1000]

    float *ph, *pxe, *phn, *pffn;
    cudaGetSymbolAddress((void**)&ph,   g_h);
    cudaGetSymbolAddress((void**)&pxe,  g_xemb);
    cudaGetSymbolAddress((void**)&phn,  g_hn);
    cudaGetSymbolAddress((void**)&pffn, g_ffn);

    dim3 blk(256);

    // embed: xemb = x @ embed_w^T + embed_b ; h = xemb
    {
        dim3 grid(H_DIM / 128, B_ROWS / 128);  // (8, 32)
        sgemm_kernel<0><<<grid, blk>>>(x, embed_w, embed_b, pxe, ph,
                                       nullptr, nullptr, B_ROWS, H_DIM, D_IN);
    }

    for (int s = 0; s < N_STEPS; s++) {
        layernorm_kernel<<<B_ROWS, blk>>>(ph, norm_w, norm_b, phn);

        // ffn_hidden = tanh(hn @ W1^T + b1)   [4096, 4096]
        {
            dim3 grid(FFN_DIM / 128, B_ROWS / 128);  // (32, 32)
            sgemm_kernel<1><<<grid, blk>>>(phn, W1_w, W1_b, pffn, nullptr,
                                           nullptr, nullptr, B_ROWS, FFN_DIM, H_DIM);
        }
        // h = 0.5*h + 0.5*(ffn @ W2^T + b2 + xemb)   [4096, 1024]
        {
            dim3 grid(H_DIM / 128, B_ROWS / 128);    // (8, 32)
            sgemm_kernel<2><<<grid, blk>>>(pffn, W2_w, W2_b, ph, nullptr,
                                           ph, pxe, B_ROWS, H_DIM, FFN_DIM);
        }
    }

    // head: out = h @ head_w^T + head_b   [4096, 1000]
    {
        dim3 grid((D_OUT + 127) / 128, B_ROWS / 128);  // (8, 32)
        sgemm_kernel<0><<<grid, blk>>>(ph, head_w, head_b, out, nullptr,
                                       nullptr, nullptr, B_ROWS, D_OUT, H_DIM);
    }
}

// round 4
// speedup vs baseline: 2.0722x; 2.0722x over previous
#include <cuda_runtime.h>
#include <math.h>

#define H_DIM 1024
#define FFN_DIM 4096
#define B_ROWS 4096
#define D_IN 784
#define D_OUT 1000
#define N_STEPS 30
#define GAMMA 0.5f
#define LN_EPS 1e-5f

// Scratch (device globals; no allocation allowed)
__device__ float g_h[(size_t)B_ROWS * H_DIM];       // 16 MB
__device__ float g_xemb[(size_t)B_ROWS * H_DIM];    // 16 MB
__device__ float g_hn[(size_t)B_ROWS * H_DIM];      // 16 MB
__device__ float g_ffn[(size_t)B_ROWS * FFN_DIM];   // 64 MB
__device__ float g_w1t[(size_t)FFN_DIM * H_DIM];    // 16 MB (tf32-rounded W1)
__device__ float g_w2t[(size_t)H_DIM * FFN_DIM];    // 16 MB (tf32-rounded W2)

// ---------------------------------------------------------------------------
// PTX helpers
// ---------------------------------------------------------------------------
__device__ __forceinline__ unsigned smem_u32(const void* p) {
    return (unsigned)__cvta_generic_to_shared(p);
}

__device__ __forceinline__ void ldsm_x4(unsigned addr, unsigned& r0, unsigned& r1,
                                        unsigned& r2, unsigned& r3) {
    asm volatile("ldmatrix.sync.aligned.m8n8.x4.shared.b16 {%0,%1,%2,%3}, [%4];"
                 : "=r"(r0), "=r"(r1), "=r"(r2), "=r"(r3) : "r"(addr));
}

__device__ __forceinline__ void mma_tf32(float* d, const unsigned* a, unsigned b0, unsigned b1) {
    asm volatile("mma.sync.aligned.m16n8k8.row.col.f32.tf32.tf32.f32 "
                 "{%0,%1,%2,%3}, {%4,%5,%6,%7}, {%8,%9}, {%0,%1,%2,%3};"
                 : "+f"(d[0]), "+f"(d[1]), "+f"(d[2]), "+f"(d[3])
                 : "r"(a[0]), "r"(a[1]), "r"(a[2]), "r"(a[3]), "r"(b0), "r"(b1));
}

__device__ __forceinline__ unsigned f2tf32(float f) {
    unsigned r;
    asm("cvt.rna.tf32.f32 %0, %1;" : "=r"(r) : "f"(f));
    return r;
}
__device__ __forceinline__ float tf32r(float f) { return __uint_as_float(f2tf32(f)); }

__device__ __forceinline__ void cp16(unsigned dst, const void* src, int srcsize) {
    asm volatile("cp.async.cg.shared.global [%0], [%1], 16, %2;"
                 :: "r"(dst), "l"(src), "r"(srcsize));
}
__device__ __forceinline__ void cp_commit() { asm volatile("cp.async.commit_group;"); }
__device__ __forceinline__ void cp_wait_all() {
    asm volatile("cp.async.wait_group 0;" ::: "memory");
}

// ---------------------------------------------------------------------------
// TF32 tensor-core GEMM: C[M,N] = epi( A[M,K] @ W[N,K]^T + bias[N] )
// 128x128 block tile, BK=16, 256 threads (8 warps, 2x4), warp tile 64x32.
// m16n8k8 tf32 mma; fragments via ldmatrix.x4; cp.async double buffer.
// Requirements: M % 128 == 0, K % 16 == 0, N % 8 == 0 (N < grid coverage OK).
// MODE 0: C = v (and C2 = v if C2 != null)
// MODE 1: C = tf32round(tanh(v))
// MODE 2: C = (1-GAMMA)*Hold + GAMMA*(v + Xemb)
// CVT: round A/W fragments to tf32 (rna) in-kernel (inputs are raw fp32).
// ---------------------------------------------------------------------------
template <int MODE, bool CVT>
__global__ __launch_bounds__(256)
void mma_gemm(const float* __restrict__ A,
              const float* __restrict__ W,
              const float* __restrict__ bias,
              float* __restrict__ C,
              float* __restrict__ C2,
              const float* __restrict__ Hold,
              const float* __restrict__ Xemb,
              int M, int N, int K)
{
    constexpr int ST = 20;                 // padded smem row stride (floats)
    constexpr int STAGE_FLOATS = 2 * 128 * ST;  // A tile + B tile per stage
    __shared__ float sm[2 * STAGE_FLOATS]; // 2 stages = 40960 B

    const int tid  = threadIdx.x;
    const int lane = tid & 31;
    const int warp = tid >> 5;
    const int wm = warp >> 2;              // 0..1
    const int wn = warp & 3;               // 0..3
    const int bm = blockIdx.y * 128;
    const int bn = blockIdx.x * 128;

    const unsigned sbase = smem_u32(sm);

    // ldmatrix per-thread base offsets (floats, within a stage)
    const int grp = lane >> 3, r8 = lane & 7;
    const int aoff = (wm * 64 + (grp & 1) * 8 + r8) * ST + (grp >> 1) * 4;
    const int boff = 128 * ST + (wn * 32 + (grp >> 1) * 8 + r8) * ST + (grp & 1) * 4;

    float acc[4][4][4];
    #pragma unroll
    for (int i = 0; i < 4; i++)
        #pragma unroll
        for (int j = 0; j < 4; j++)
            #pragma unroll
            for (int r = 0; r < 4; r++) acc[i][j][r] = 0.0f;

    // -------- stage loader: 4 x 16B cp.async per thread (A:2, B:2) --------
    auto stage_load = [&](int k0, int stage) {
        const unsigned sb = sbase + (unsigned)(stage * STAGE_FLOATS) * 4u;
        #pragma unroll
        for (int h = 0; h < 2; h++) {
            int c = tid + h * 256;           // 0..511
            int row = c >> 2, kc = c & 3;
            cp16(sb + (unsigned)(row * ST + kc * 4) * 4u,
                 A + (size_t)(bm + row) * K + k0 + kc * 4, 16);
        }
        #pragma unroll
        for (int h = 0; h < 2; h++) {
            int c = tid + h * 256;
            int row = c >> 2, kc = c & 3;
            int ok = ((bn + row) < N) ? 16 : 0;   // zfill rows beyond N
            cp16(sb + (unsigned)(128 * ST + row * ST + kc * 4) * 4u,
                 W + (size_t)(bn + row) * K + k0 + kc * 4, ok);
        }
    };

    const int niter = K >> 4;
    stage_load(0, 0);
    cp_commit();

    for (int it = 0; it < niter; ++it) {
        cp_wait_all();
        __syncthreads();
        if (it + 1 < niter) {
            stage_load((it + 1) << 4, (it + 1) & 1);
            cp_commit();
        }
        const unsigned stb = sbase + (unsigned)((it & 1) * STAGE_FLOATS) * 4u;

        #pragma unroll
        for (int ks = 0; ks < 2; ++ks) {
            unsigned a[4][4], b[2][4];
            #pragma unroll
            for (int im = 0; im < 4; im++)
                ldsm_x4(stb + (unsigned)(aoff + im * 16 * ST + ks * 8) * 4u,
                        a[im][0], a[im][1], a[im][2], a[im][3]);
            #pragma unroll
            for (int p = 0; p < 2; p++)
                ldsm_x4(stb + (unsigned)(boff + p * 16 * ST + ks * 8) * 4u,
                        b[p][0], b[p][1], b[p][2], b[p][3]);

            if (CVT) {
                #pragma unroll
                for (int im = 0; im < 4; im++)
                    #pragma unroll
                    for (int r = 0; r < 4; r++)
                        a[im][r] = f2tf32(__uint_as_float(a[im][r]));
                #pragma unroll
                for (int p = 0; p < 2; p++)
                    #pragma unroll
                    for (int r = 0; r < 4; r++)
                        b[p][r] = f2tf32(__uint_as_float(b[p][r]));
            }

            #pragma unroll
            for (int im = 0; im < 4; im++)
                #pragma unroll
                for (int jn = 0; jn < 4; jn++)
                    mma_tf32(acc[im][jn], a[im],
                             b[jn >> 1][(jn & 1) * 2], b[jn >> 1][(jn & 1) * 2 + 1]);
        }
    }

    // -------- epilogue --------
    #pragma unroll
    for (int im = 0; im < 4; im++) {
        const int r0 = bm + wm * 64 + im * 16 + (lane >> 2);
        const int r1 = r0 + 8;
        #pragma unroll
        for (int jn = 0; jn < 4; jn++) {
            const int c = bn + wn * 32 + jn * 8 + (lane & 3) * 2;
            if (c < N) {
                const float2 bb = *(const float2*)&bias[c];
                float v00 = acc[im][jn][0] + bb.x;
                float v01 = acc[im][jn][1] + bb.y;
                float v10 = acc[im][jn][2] + bb.x;
                float v11 = acc[im][jn][3] + bb.y;
                const size_t i0 = (size_t)r0 * N + c;
                const size_t i1 = (size_t)r1 * N + c;
                if (MODE == 0) {
                    *(float2*)&C[i0] = make_float2(v00, v01);
                    *(float2*)&C[i1] = make_float2(v10, v11);
                    if (C2) {
                        *(float2*)&C2[i0] = make_float2(v00, v01);
                        *(float2*)&C2[i1] = make_float2(v10, v11);
                    }
                } else if (MODE == 1) {
                    *(float2*)&C[i0] = make_float2(tf32r(tanhf(v00)), tf32r(tanhf(v01)));
                    *(float2*)&C[i1] = make_float2(tf32r(tanhf(v10)), tf32r(tanhf(v11)));
                } else {  // MODE 2
                    const float2 h0 = *(const float2*)&Hold[i0];
                    const float2 h1 = *(const float2*)&Hold[i1];
                    const float2 x0 = *(const float2*)&Xemb[i0];
                    const float2 x1 = *(const float2*)&Xemb[i1];
                    *(float2*)&C[i0] = make_float2(
                        (1.0f - GAMMA) * h0.x + GAMMA * (v00 + x0.x),
                        (1.0f - GAMMA) * h0.y + GAMMA * (v01 + x0.y));
                    *(float2*)&C[i1] = make_float2(
                        (1.0f - GAMMA) * h1.x + GAMMA * (v10 + x1.x),
                        (1.0f - GAMMA) * h1.y + GAMMA * (v11 + x1.y));
                }
            }
        }
    }
}

// ---------------------------------------------------------------------------
// One-shot weight rounding to tf32 (rna), stored as fp32 bit patterns.
// ---------------------------------------------------------------------------
__global__ __launch_bounds__(256)
void round_tf32_kernel(const float* __restrict__ in, float* __restrict__ out, int n)
{
    int i = (blockIdx.x * 256 + threadIdx.x) * 4;
    if (i < n) {
        float4 v = *(const float4*)&in[i];
        v.x = tf32r(v.x); v.y = tf32r(v.y); v.z = tf32r(v.z); v.w = tf32r(v.w);
        *(float4*)&out[i] = v;
    }
}

// ---------------------------------------------------------------------------
// LayerNorm over rows of [B_ROWS, 1024]; output pre-rounded to tf32.
// ---------------------------------------------------------------------------
__global__ __launch_bounds__(256)
void layernorm_kernel(const float* __restrict__ Hin,
                      const float* __restrict__ w,
                      const float* __restrict__ b,
                      float* __restrict__ Out)
{
    __shared__ float ssum[8], ssq[8];
    const int row = blockIdx.x;
    const int tid = threadIdx.x;

    const float4* hp = (const float4*)(Hin + (size_t)row * H_DIM);
    float4 v = hp[tid];
    float s = v.x + v.y + v.z + v.w;
    float q = v.x * v.x + v.y * v.y + v.z * v.z + v.w * v.w;
    #pragma unroll
    for (int o = 16; o > 0; o >>= 1) {
        s += __shfl_xor_sync(0xFFFFFFFFu, s, o);
        q += __shfl_xor_sync(0xFFFFFFFFu, q, o);
    }
    const int warp = tid >> 5, lane = tid & 31;
    if (lane == 0) { ssum[warp] = s; ssq[warp] = q; }
    __syncthreads();
    float ts = 0.f, tq = 0.f;
    #pragma unroll
    for (int i = 0; i < 8; i++) { ts += ssum[i]; tq += ssq[i]; }

    const float mu  = ts * (1.0f / H_DIM);
    const float var = tq * (1.0f / H_DIM) - mu * mu;
    const float inv = rsqrtf(var + LN_EPS);

    float4 wv = ((const float4*)w)[tid];
    float4 bv = ((const float4*)b)[tid];
    float4 o;
    o.x = tf32r((v.x - mu) * inv * wv.x + bv.x);
    o.y = tf32r((v.y - mu) * inv * wv.y + bv.y);
    o.z = tf32r((v.z - mu) * inv * wv.z + bv.z);
    o.w = tf32r((v.w - mu) * inv * wv.w + bv.w);
    ((float4*)(Out + (size_t)row * H_DIM))[tid] = o;
}

// ---------------------------------------------------------------------------
extern "C" void kernel_launch(void* const* d_in, const int* in_sizes, int n_in,
                              void* d_out, int out_size)
{
    const float* x       = (const float*)d_in[0];   // [4096, 784]
    const float* embed_w = (const float*)d_in[1];   // [1024, 784]
    const float* embed_b = (const float*)d_in[2];   // [1024]
    const float* W1_w    = (const float*)d_in[3];   // [4096, 1024]
    const float* W1_b    = (const float*)d_in[4];   // [4096]
    const float* W2_w    = (const float*)d_in[5];   // [1024, 4096]
    const float* W2_b    = (const float*)d_in[6];   // [1024]
    const float* norm_w  = (const float*)d_in[7];   // [1024]
    const float* norm_b  = (const float*)d_in[8];   // [1024]
    const float* head_w  = (const float*)d_in[9];   // [1000, 1024]
    const float* head_b  = (const float*)d_in[10];  // [1000]
    // d_in[11] = steps (device scalar; fixed at 30 by problem setup)

    float* out = (float*)d_out;                     // [4096, 1000]

    float *ph, *pxe, *phn, *pffn, *pw1, *pw2;
    cudaGetSymbolAddress((void**)&ph,   g_h);
    cudaGetSymbolAddress((void**)&pxe,  g_xemb);
    cudaGetSymbolAddress((void**)&phn,  g_hn);
    cudaGetSymbolAddress((void**)&pffn, g_ffn);
    cudaGetSymbolAddress((void**)&pw1,  g_w1t);
    cudaGetSymbolAddress((void**)&pw2,  g_w2t);

    dim3 blk(256);

    // Pre-round weights to tf32 once (part of graph; idempotent)
    {
        int n = FFN_DIM * H_DIM;  // 4M each
        round_tf32_kernel<<<n / (256 * 4), blk>>>(W1_w, pw1, n);
        round_tf32_kernel<<<n / (256 * 4), blk>>>(W2_w, pw2, n);
    }

    // embed: xemb = x @ embed_w^T + embed_b ; h = xemb   (raw fp32 -> CVT)
    {
        dim3 grid(H_DIM / 128, B_ROWS / 128);  // (8, 32)
        mma_gemm<0, true><<<grid, blk>>>(x, embed_w, embed_b, pxe, ph,
                                         nullptr, nullptr, B_ROWS, H_DIM, D_IN);
    }

    for (int s = 0; s < N_STEPS; s++) {
        layernorm_kernel<<<B_ROWS, blk>>>(ph, norm_w, norm_b, phn);

        // ffn_hidden = tanh(hn @ W1^T + b1)   [4096, 4096], inputs pre-rounded
        {
            dim3 grid(FFN_DIM / 128, B_ROWS / 128);  // (32, 32)
            mma_gemm<1, false><<<grid, blk>>>(phn, pw1, W1_b, pffn, nullptr,
                                              nullptr, nullptr, B_ROWS, FFN_DIM, H_DIM);
        }
        // h = 0.5*h + 0.5*(ffn @ W2^T + b2 + xemb)   [4096, 1024]
        {
            dim3 grid(H_DIM / 128, B_ROWS / 128);    // (8, 32)
            mma_gemm<2, false><<<grid, blk>>>(pffn, pw2, W2_b, ph, nullptr,
                                              ph, pxe, B_ROWS, H_DIM, FFN_DIM);
        }
    }

    // head: out = h @ head_w^T + head_b   [4096, 1000]  (raw fp32 -> CVT)
    {
        dim3 grid((D_OUT + 127) / 128, B_ROWS / 128);  // (8, 32)
        mma_gemm<0, true><<<grid, blk>>>(ph, head_w, head_b, out, nullptr,
                                         nullptr, nullptr, B_ROWS, D_OUT, H_DIM);
    }
}

// round 6
// speedup vs baseline: 6.7486x; 3.2567x over previous
#include <cuda_runtime.h>
#include <cuda_fp16.h>
#include <math.h>
#include <stdint.h>

#define H_DIM 1024
#define FFN_DIM 4096
#define B_ROWS 4096
#define D_IN 784
#define K_EMB 800
#define D_OUT 1000
#define N_STEPS 30
#define LN_EPS 1e-5f

// ---------------- scratch (device globals; no allocation allowed) ----------
__device__ float  g_h[(size_t)B_ROWS * H_DIM];        // 16 MB fp32 state
__device__ float  g_xemb[(size_t)B_ROWS * H_DIM];     // 16 MB fp32
__device__ __half g_hn[(size_t)B_ROWS * H_DIM];       // 8 MB  (LN out / head A)
__device__ __half g_ffn[(size_t)B_ROWS * FFN_DIM];    // 32 MB (tanh out)
__device__ __half g_w1h[(size_t)FFN_DIM * H_DIM];     // 8 MB
__device__ __half g_w2h[(size_t)H_DIM * FFN_DIM];     // 8 MB
__device__ __half g_xh [(size_t)B_ROWS * K_EMB];      // 6.5 MB (x padded)
__device__ __half g_ewh[(size_t)H_DIM * K_EMB];       // 1.6 MB (embed_w padded)
__device__ __half g_hwh[(size_t)D_OUT * H_DIM];       // 2 MB   (head_w)

// ---------------- PTX helpers ----------------------------------------------
__device__ __forceinline__ uint32_t smem_u32(const void* p) {
    return (uint32_t)__cvta_generic_to_shared(p);
}
__device__ __forceinline__ void cp16(uint32_t dst, const void* src, int sz) {
    asm volatile("cp.async.cg.shared.global [%0], [%1], 16, %2;"
                 :: "r"(dst), "l"(src), "r"(sz));
}
__device__ __forceinline__ void cp_commit() { asm volatile("cp.async.commit_group;"); }
__device__ __forceinline__ void cp_wait1() {
    asm volatile("cp.async.wait_group 1;" ::: "memory");
}
__device__ __forceinline__ void ldsm_x4(uint32_t addr, uint32_t& r0, uint32_t& r1,
                                        uint32_t& r2, uint32_t& r3) {
    asm volatile("ldmatrix.sync.aligned.m8n8.x4.shared.b16 {%0,%1,%2,%3}, [%4];"
                 : "=r"(r0), "=r"(r1), "=r"(r2), "=r"(r3) : "r"(addr));
}
__device__ __forceinline__ void mma_f16(float* d, const uint32_t* a, uint32_t b0, uint32_t b1) {
    asm volatile("mma.sync.aligned.m16n8k16.row.col.f32.f16.f16.f32 "
                 "{%0,%1,%2,%3}, {%4,%5,%6,%7}, {%8,%9}, {%0,%1,%2,%3};"
                 : "+f"(d[0]), "+f"(d[1]), "+f"(d[2]), "+f"(d[3])
                 : "r"(a[0]), "r"(a[1]), "r"(a[2]), "r"(a[3]), "r"(b0), "r"(b1));
}

// ---------------------------------------------------------------------------
// FP16 tensor GEMM: C[M,N] = epi( A[M,K] @ W[N,K]^T + bias[N] )
// 128x128 CTA tile, BK=32, 3-stage cp.async ring, 256 threads (8 warps 2x4),
// warp tile 64x32, m16n8k16 f16 mma, fp32 accumulators.
// M%128==0, K%32==0; N guarded (zfill + epilogue guard).
// MODE 0: C(fp32)=v, C2(fp32)=v if set
// MODE 1: C(fp16)=half(tanh(v))
// MODE 2: C(fp32)=0.5*Hold + 0.5*(v + Xemb)
// ---------------------------------------------------------------------------
#define ST 40                           // smem row stride in halves
#define TILE_BYTES (128 * ST * 2)       // 10240
#define STAGE_BYTES (2 * TILE_BYTES)    // 20480
#define SMEM_BYTES (3 * STAGE_BYTES)    // 61440

template <int MODE>
__global__ __launch_bounds__(256)
void f16_gemm(const __half* __restrict__ A, const __half* __restrict__ W,
              const float* __restrict__ bias, void* __restrict__ Cv,
              float* __restrict__ C2, const float* __restrict__ Hold,
              const float* __restrict__ Xemb, int M, int N, int K)
{
    extern __shared__ char smem[];
    const uint32_t sb = smem_u32(smem);
    const int tid  = threadIdx.x;
    const int lane = tid & 31;
    const int warp = tid >> 5;
    const int wm = warp >> 2;           // 0..1
    const int wn = warp & 3;            // 0..3
    const int bm = blockIdx.y * 128;
    const int bn = blockIdx.x * 128;
    const int nst = K >> 5;

    // ldmatrix per-thread byte offsets within a stage
    const int grp = lane >> 3, r8 = lane & 7;
    const uint32_t aoff = (uint32_t)(((wm * 64 + (lane & 15)) * ST + (lane >> 4) * 8) * 2);
    const uint32_t boff = (uint32_t)TILE_BYTES +
        (uint32_t)(((wn * 32 + (grp >> 1) * 8 + r8) * ST + (grp & 1) * 8) * 2);

    float acc[4][4][4];
    #pragma unroll
    for (int i = 0; i < 4; i++)
        #pragma unroll
        for (int j = 0; j < 4; j++)
            #pragma unroll
            for (int r = 0; r < 4; r++) acc[i][j][r] = 0.0f;

    auto load_stage = [&](int s) {
        if (s >= nst) return;
        const uint32_t stb = sb + (uint32_t)(s % 3) * STAGE_BYTES;
        const int k0 = s << 5;
        #pragma unroll
        for (int i = 0; i < 4; i++) {
            const int c = tid + (i << 8);   // 0..1023
            if (c < 512) {                  // A: 128 rows x 4 x 16B
                const int row = c >> 2, kc = c & 3;
                cp16(stb + (uint32_t)((row * ST + kc * 8) * 2),
                     A + (size_t)(bm + row) * K + k0 + kc * 8, 16);
            } else {                        // W: 128 rows x 4 x 16B (zfill > N)
                const int c2 = c - 512;
                const int row = c2 >> 2, kc = c2 & 3;
                const int ok = ((bn + row) < N) ? 16 : 0;
                cp16(stb + (uint32_t)TILE_BYTES + (uint32_t)((row * ST + kc * 8) * 2),
                     W + (size_t)(bn + row) * K + k0 + kc * 8, ok);
            }
        }
    };

    load_stage(0); cp_commit();
    load_stage(1); cp_commit();

    for (int s = 0; s < nst; s++) {
        cp_wait1();
        __syncthreads();
        const uint32_t stb = sb + (uint32_t)(s % 3) * STAGE_BYTES;

        #pragma unroll
        for (int ks = 0; ks < 2; ks++) {
            const uint32_t ko = (uint32_t)(ks * 32);  // 16 halves
            uint32_t a[4][4], b[2][4];
            #pragma unroll
            for (int im = 0; im < 4; im++)
                ldsm_x4(stb + aoff + (uint32_t)(im * 16 * ST * 2) + ko,
                        a[im][0], a[im][1], a[im][2], a[im][3]);
            #pragma unroll
            for (int p = 0; p < 2; p++)
                ldsm_x4(stb + boff + (uint32_t)(p * 16 * ST * 2) + ko,
                        b[p][0], b[p][1], b[p][2], b[p][3]);
            #pragma unroll
            for (int im = 0; im < 4; im++)
                #pragma unroll
                for (int jn = 0; jn < 4; jn++)
                    mma_f16(acc[im][jn], a[im],
                            b[jn >> 1][(jn & 1) * 2], b[jn >> 1][(jn & 1) * 2 + 1]);
        }
        load_stage(s + 2);
        cp_commit();
    }

    // -------- epilogue --------
    #pragma unroll
    for (int im = 0; im < 4; im++) {
        const int r0 = bm + wm * 64 + im * 16 + (lane >> 2);
        const int r1 = r0 + 8;
        #pragma unroll
        for (int jn = 0; jn < 4; jn++) {
            const int c = bn + wn * 32 + jn * 8 + (lane & 3) * 2;
            if (c < N) {
                const float2 bb = *(const float2*)&bias[c];
                float v00 = acc[im][jn][0] + bb.x;
                float v01 = acc[im][jn][1] + bb.y;
                float v10 = acc[im][jn][2] + bb.x;
                float v11 = acc[im][jn][3] + bb.y;
                const size_t i0 = (size_t)r0 * N + c;
                const size_t i1 = (size_t)r1 * N + c;
                if (MODE == 0) {
                    float* C = (float*)Cv;
                    *(float2*)&C[i0] = make_float2(v00, v01);
                    *(float2*)&C[i1] = make_float2(v10, v11);
                    if (C2) {
                        *(float2*)&C2[i0] = make_float2(v00, v01);
                        *(float2*)&C2[i1] = make_float2(v10, v11);
                    }
                } else if (MODE == 1) {
                    __half* C = (__half*)Cv;
                    *(__half2*)&C[i0] = __floats2half2_rn(tanhf(v00), tanhf(v01));
                    *(__half2*)&C[i1] = __floats2half2_rn(tanhf(v10), tanhf(v11));
                } else {
                    float* C = (float*)Cv;
                    const float2 h0 = *(const float2*)&Hold[i0];
                    const float2 h1 = *(const float2*)&Hold[i1];
                    const float2 x0 = *(const float2*)&Xemb[i0];
                    const float2 x1 = *(const float2*)&Xemb[i1];
                    *(float2*)&C[i0] = make_float2(0.5f * h0.x + 0.5f * (v00 + x0.x),
                                                   0.5f * h0.y + 0.5f * (v01 + x0.y));
                    *(float2*)&C[i1] = make_float2(0.5f * h1.x + 0.5f * (v10 + x1.x),
                                                   0.5f * h1.y + 0.5f * (v11 + x1.y));
                }
            }
        }
    }
}

// ---------------------------------------------------------------------------
// fp32 -> fp16 convert with K-padding: in[rows,Kin] -> out[rows,Kout]
// Kin%4==0, Kout%4==0; cols >= Kin are zero.
// ---------------------------------------------------------------------------
__global__ __launch_bounds__(256)
void cvt_pad_kernel(const float* __restrict__ in, __half* __restrict__ out,
                    int Kin, int Kout, int total_out)
{
    const int e = (blockIdx.x * 256 + threadIdx.x) * 4;
    if (e >= total_out) return;
    const int row = e / Kout, col = e % Kout;
    __half2 lo = __floats2half2_rn(0.f, 0.f), hi = lo;
    if (col < Kin) {
        const float4 v = *(const float4*)(in + (size_t)row * Kin + col);
        lo = __floats2half2_rn(v.x, v.y);
        hi = __floats2half2_rn(v.z, v.w);
    }
    __half2* o = (__half2*)(out + (size_t)row * Kout + col);
    o[0] = lo; o[1] = hi;
}

// ---------------------------------------------------------------------------
// LayerNorm over rows of [B_ROWS, 1024]; fp32 in, fp16 out.
// ---------------------------------------------------------------------------
__global__ __launch_bounds__(256)
void layernorm_kernel(const float* __restrict__ Hin,
                      const float* __restrict__ w,
                      const float* __restrict__ b,
                      __half* __restrict__ Out)
{
    __shared__ float ssum[8], ssq[8];
    const int row = blockIdx.x;
    const int tid = threadIdx.x;

    const float4 v = ((const float4*)(Hin + (size_t)row * H_DIM))[tid];
    float s = v.x + v.y + v.z + v.w;
    float q = v.x * v.x + v.y * v.y + v.z * v.z + v.w * v.w;
    #pragma unroll
    for (int o = 16; o > 0; o >>= 1) {
        s += __shfl_xor_sync(0xFFFFFFFFu, s, o);
        q += __shfl_xor_sync(0xFFFFFFFFu, q, o);
    }
    const int warp = tid >> 5, lane = tid & 31;
    if (lane == 0) { ssum[warp] = s; ssq[warp] = q; }
    __syncthreads();
    float ts = 0.f, tq = 0.f;
    #pragma unroll
    for (int i = 0; i < 8; i++) { ts += ssum[i]; tq += ssq[i]; }

    const float mu  = ts * (1.0f / H_DIM);
    const float var = tq * (1.0f / H_DIM) - mu * mu;
    const float inv = rsqrtf(var + LN_EPS);

    const float4 wv = ((const float4*)w)[tid];
    const float4 bv = ((const float4*)b)[tid];
    __half2 lo = __floats2half2_rn((v.x - mu) * inv * wv.x + bv.x,
                                   (v.y - mu) * inv * wv.y + bv.y);
    __half2 hi = __floats2half2_rn((v.z - mu) * inv * wv.z + bv.z,
                                   (v.w - mu) * inv * wv.w + bv.w);
    __half2* o = (__half2*)(Out + (size_t)row * H_DIM + tid * 4);
    o[0] = lo; o[1] = hi;
}

// ---------------------------------------------------------------------------
extern "C" void kernel_launch(void* const* d_in, const int* in_sizes, int n_in,
                              void* d_out, int out_size)
{
    const float* x       = (const float*)d_in[0];
    const float* embed_w = (const float*)d_in[1];
    const float* embed_b = (const float*)d_in[2];
    const float* W1_w    = (const float*)d_in[3];
    const float* W1_b    = (const float*)d_in[4];
    const float* W2_w    = (const float*)d_in[5];
    const float* W2_b    = (const float*)d_in[6];
    const float* norm_w  = (const float*)d_in[7];
    const float* norm_b  = (const float*)d_in[8];
    const float* head_w  = (const float*)d_in[9];
    const float* head_b  = (const float*)d_in[10];
    float* out = (float*)d_out;                     // [4096, 1000]

    float  *ph, *pxe;
    __half *phn, *pffn, *pw1, *pw2, *pxh, *pewh, *phwh;
    cudaGetSymbolAddress((void**)&ph,   g_h);
    cudaGetSymbolAddress((void**)&pxe,  g_xemb);
    cudaGetSymbolAddress((void**)&phn,  g_hn);
    cudaGetSymbolAddress((void**)&pffn, g_ffn);
    cudaGetSymbolAddress((void**)&pw1,  g_w1h);
    cudaGetSymbolAddress((void**)&pw2,  g_w2h);
    cudaGetSymbolAddress((void**)&pxh,  g_xh);
    cudaGetSymbolAddress((void**)&pewh, g_ewh);
    cudaGetSymbolAddress((void**)&phwh, g_hwh);

    cudaFuncSetAttribute(f16_gemm<0>, cudaFuncAttributeMaxDynamicSharedMemorySize, SMEM_BYTES);
    cudaFuncSetAttribute(f16_gemm<1>, cudaFuncAttributeMaxDynamicSharedMemorySize, SMEM_BYTES);
    cudaFuncSetAttribute(f16_gemm<2>, cudaFuncAttributeMaxDynamicSharedMemorySize, SMEM_BYTES);

    dim3 blk(256);
    auto rgrid = [](int total) { return dim3((total / 4 + 255) / 256); };

    // one-shot fp16 conversions (idempotent; part of graph)
    cvt_pad_kernel<<<rgrid(B_ROWS * K_EMB), blk>>>(x, pxh, D_IN, K_EMB, B_ROWS * K_EMB);
    cvt_pad_kernel<<<rgrid(H_DIM * K_EMB), blk>>>(embed_w, pewh, D_IN, K_EMB, H_DIM * K_EMB);
    cvt_pad_kernel<<<rgrid(FFN_DIM * H_DIM), blk>>>(W1_w, pw1, H_DIM, H_DIM, FFN_DIM * H_DIM);
    cvt_pad_kernel<<<rgrid(H_DIM * FFN_DIM), blk>>>(W2_w, pw2, FFN_DIM, FFN_DIM, H_DIM * FFN_DIM);
    cvt_pad_kernel<<<rgrid(D_OUT * H_DIM), blk>>>(head_w, phwh, H_DIM, H_DIM, D_OUT * H_DIM);

    // embed: xemb = xh @ ewh^T + embed_b ; h = xemb
    {
        dim3 grid(H_DIM / 128, B_ROWS / 128);  // (8, 32)
        f16_gemm<0><<<grid, blk, SMEM_BYTES>>>(pxh, pewh, embed_b, pxe, ph,
                                               nullptr, nullptr, B_ROWS, H_DIM, K_EMB);
    }

    for (int s = 0; s < N_STEPS; s++) {
        layernorm_kernel<<<B_ROWS, blk>>>(ph, norm_w, norm_b, phn);
        // ffn = tanh(hn @ W1^T + b1)  -> fp16
        {
            dim3 grid(FFN_DIM / 128, B_ROWS / 128);  // (32, 32)
            f16_gemm<1><<<grid, blk, SMEM_BYTES>>>(phn, pw1, W1_b, pffn, nullptr,
                                                   nullptr, nullptr, B_ROWS, FFN_DIM, H_DIM);
        }
        // h = 0.5h + 0.5(ffn @ W2^T + b2 + xemb)
        {
            dim3 grid(H_DIM / 128, B_ROWS / 128);    // (8, 32)
            f16_gemm<2><<<grid, blk, SMEM_BYTES>>>(pffn, pw2, W2_b, ph, nullptr,
                                                   ph, pxe, B_ROWS, H_DIM, FFN_DIM);
        }
    }

    // head: out = half(h) @ hwh^T + head_b
    cvt_pad_kernel<<<rgrid(B_ROWS * H_DIM), blk>>>(ph, phn, H_DIM, H_DIM, B_ROWS * H_DIM);
    {
        dim3 grid((D_OUT + 127) / 128, B_ROWS / 128);  // (8, 32)
        f16_gemm<0><<<grid, blk, SMEM_BYTES>>>(phn, phwh, head_b, out, nullptr,
                                               nullptr, nullptr, B_ROWS, D_OUT, H_DIM);
    }
}